// round 10
// baseline (speedup 1.0000x reference)
#include <cuda_runtime.h>
#include <cuda_fp16.h>
#include <cstdint>
#include <cstddef>

// Problem constants
#define BJ   69632           // 4096*17 rows
#define NB   4096
#define NJ   17
#define ND   512
#define NH   8
#define NDK  64

// ---------------- device scratch ------------------------------------------------
__device__ __half g_src_h[(size_t)BJ * 512];   // src as half
__device__ __half g_qkv  [(size_t)BJ * 1536];  // fused Q|K|V (half)
__device__ __half g_o    [(size_t)BJ * 512];   // attention output (half)
__device__ __half g_x_h  [(size_t)BJ * 512];   // LN1 output (half)
__device__ __half g_Wqkv[1536 * 512];          // transposed [N][K] half
__device__ float  g_bqkv[1536];
__device__ __half g_Wo_t[512 * 512];           // transposed [N][K] half
__device__ __half g_Wcat[512 * 1024];          // [N=512][K=1024]: [W0-W1 ; W1]^T half
__device__ float  g_A[NJ * NJ];

// ---------------- helpers -------------------------------------------------------
__device__ __forceinline__ uint32_t smem_u32(const void* p) {
    uint32_t a;
    asm("{ .reg .u64 t; cvta.to.shared.u64 t, %1; cvt.u32.u64 %0, t; }" : "=r"(a) : "l"(p));
    return a;
}
__device__ __forceinline__ void cp16(uint32_t saddr, const void* gptr) {
    asm volatile("cp.async.cg.shared.global [%0], [%1], 16;" :: "r"(saddr), "l"(gptr));
}
__device__ __forceinline__ void cp_commit() { asm volatile("cp.async.commit_group;" ::: "memory"); }
__device__ __forceinline__ void cp_wait1()  { asm volatile("cp.async.wait_group 1;" ::: "memory"); }
__device__ __forceinline__ void cp_wait0()  { asm volatile("cp.async.wait_group 0;" ::: "memory"); }

__device__ __forceinline__ void ldsm4(uint32_t* r, uint32_t addr) {
    asm volatile("ldmatrix.sync.aligned.m8n8.x4.shared.b16 {%0,%1,%2,%3}, [%4];"
        : "=r"(r[0]), "=r"(r[1]), "=r"(r[2]), "=r"(r[3]) : "r"(addr));
}
__device__ __forceinline__ void mma_f16(float* d, const uint32_t* a, const uint32_t* b) {
    asm volatile(
        "mma.sync.aligned.m16n8k16.row.col.f32.f16.f16.f32 "
        "{%0,%1,%2,%3}, {%4,%5,%6,%7}, {%8,%9}, {%0,%1,%2,%3};"
        : "+f"(d[0]), "+f"(d[1]), "+f"(d[2]), "+f"(d[3])
        : "r"(a[0]), "r"(a[1]), "r"(a[2]), "r"(a[3]), "r"(b[0]), "r"(b[1]));
}

// ================= fp16 mma.sync GEMM: C[M,N] = A[M,512] @ Bt[N,512]^T (+bias) ==
#define STAGE_BYTES 32768
#define GEMM_SMEM   (3 * STAGE_BYTES)

__global__ __launch_bounds__(256, 2) void tc_gemm(const __half* __restrict__ A,
                                                  const __half* __restrict__ Bt,
                                                  const float* __restrict__ bias,
                                                  __half* __restrict__ C, int N) {
    extern __shared__ char smem[];
    const uint32_t sb = smem_u32(smem);
    const int tid  = threadIdx.x;
    const int lane = tid & 31;
    const int wid  = tid >> 5;
    const int warp_m = (wid & 1) * 64;
    const int warp_n = (wid >> 1) * 32;
    const int l7 = lane & 7;
    const int a_row_base = warp_m + l7 + ((lane & 8) ? 8 : 0);
    const int a_cc_add = (lane & 16) ? 1 : 0;
    const int b_row_base = warp_n + l7 + ((lane & 16) ? 8 : 0);
    const int b_cc_add = (lane & 8) ? 1 : 0;

    const __half* Abase = A  + (size_t)blockIdx.y * 128 * 512;
    const __half* Bbase = Bt + (size_t)blockIdx.x * 128 * 512;

    auto issue = [&](int t) {
        const int buf = t % 3;
        const uint32_t sA = sb + buf * STAGE_BYTES;
        const uint32_t sB = sA + 16384;
        const __half* Ab = Abase + t * 64;
        const __half* Bb = Bbase + t * 64;
        #pragma unroll
        for (int ll = 0; ll < 4; ++ll) {
            int id = tid + ll * 256, row = id >> 3, cc = id & 7;
            cp16(sA + row * 128 + ((cc ^ (row & 7)) << 4), Ab + (size_t)row * 512 + cc * 8);
        }
        #pragma unroll
        for (int ll = 0; ll < 4; ++ll) {
            int id = tid + ll * 256, row = id >> 3, cc = id & 7;
            cp16(sB + row * 128 + ((cc ^ (row & 7)) << 4), Bb + (size_t)row * 512 + cc * 8);
        }
        cp_commit();
    };

    float acc[4][4][4];
    #pragma unroll
    for (int i = 0; i < 4; ++i)
        #pragma unroll
        for (int j = 0; j < 4; ++j)
            #pragma unroll
            for (int q = 0; q < 4; ++q) acc[i][j][q] = 0.f;

    issue(0);
    issue(1);

    #pragma unroll 1
    for (int t = 0; t < 8; ++t) {
        if (t < 7) cp_wait1(); else cp_wait0();
        __syncthreads();
        if (t + 2 < 8) issue(t + 2);

        const int buf = t % 3;
        const uint32_t sA = sb + buf * STAGE_BYTES;
        const uint32_t sB = sA + 16384;

        #pragma unroll
        for (int q = 0; q < 4; ++q) {
            const int kc = 2 * q;
            uint32_t af[4][4], bf[2][4];
            #pragma unroll
            for (int i = 0; i < 4; ++i)
                ldsm4(af[i], sA + (uint32_t)(a_row_base + i * 16) * 128 +
                              (uint32_t)(((kc + a_cc_add) ^ l7) << 4));
            #pragma unroll
            for (int j2 = 0; j2 < 2; ++j2)
                ldsm4(bf[j2], sB + (uint32_t)(b_row_base + j2 * 16) * 128 +
                               (uint32_t)(((kc + b_cc_add) ^ l7) << 4));
            #pragma unroll
            for (int i = 0; i < 4; ++i)
                #pragma unroll
                for (int j = 0; j < 4; ++j)
                    mma_f16(acc[i][j], af[i], &bf[j >> 1][(j & 1) * 2]);
        }
    }

    const size_t rowBase = (size_t)blockIdx.y * 128 + warp_m + (lane >> 2);
    const int colBase = blockIdx.x * 128 + warp_n + (lane & 3) * 2;
    #pragma unroll
    for (int i = 0; i < 4; ++i) {
        #pragma unroll
        for (int j = 0; j < 4; ++j) {
            size_t m0 = rowBase + i * 16;
            int n0 = colBase + j * 8;
            float b0 = bias[n0], b1 = bias[n0 + 1];
            *(__half2*)(C + m0 * (size_t)N + n0) =
                __floats2half2_rn(acc[i][j][0] + b0, acc[i][j][1] + b1);
            *(__half2*)(C + (m0 + 8) * (size_t)N + n0) =
                __floats2half2_rn(acc[i][j][2] + b0, acc[i][j][3] + b1);
        }
    }
}

// ===== LNG1: fused Wo-GEMM + bias + residual(src fp32) + LN -> half =============
// BM=64, BN=512, BK=64, 512 threads (16 warps 2x8), warp tile 32x64.
#define LNG_STAGE (8192 + 65536)
#define LNG_SMEM  (3 * LNG_STAGE)

__global__ __launch_bounds__(512) void ln_gemm1(const __half* __restrict__ A,
                                                const __half* __restrict__ Bt,
                                                const float* __restrict__ bias,
                                                const float* __restrict__ resid,
                                                const float* __restrict__ gam,
                                                const float* __restrict__ bet,
                                                __half* __restrict__ outp) {
    constexpr int K = 512;
    extern __shared__ char smem[];
    const uint32_t sb = smem_u32(smem);
    const int tid  = threadIdx.x;
    const int lane = tid & 31;
    const int wid  = tid >> 5;
    const int warp_m = (wid & 1) * 32;
    const int wid_n  = wid >> 1;
    const int warp_n = wid_n * 64;
    const int l7 = lane & 7;
    const int a_row_base = warp_m + l7 + ((lane & 8) ? 8 : 0);
    const int a_cc_add = (lane & 16) ? 1 : 0;
    const int b_row_base = warp_n + l7 + ((lane & 16) ? 8 : 0);
    const int b_cc_add = (lane & 8) ? 1 : 0;

    const size_t rowBlk = (size_t)blockIdx.x * 64;
    const __half* Abase = A + rowBlk * K;

    auto issue = [&](int t) {
        const int buf = t % 3;
        const uint32_t sA = sb + buf * LNG_STAGE;
        const uint32_t sB = sA + 8192;
        const __half* Ab = Abase + t * 64;
        const __half* Bb = Bt + t * 64;
        {
            int row = tid >> 3, cc = tid & 7;
            cp16(sA + row * 128 + ((cc ^ (row & 7)) << 4), Ab + (size_t)row * K + cc * 8);
        }
        #pragma unroll
        for (int ll = 0; ll < 8; ++ll) {
            int id = tid + ll * 512, row = id >> 3, cc = id & 7;
            cp16(sB + row * 128 + ((cc ^ (row & 7)) << 4), Bb + (size_t)row * K + cc * 8);
        }
        cp_commit();
    };

    float acc[2][8][4];
    #pragma unroll
    for (int i = 0; i < 2; ++i)
        #pragma unroll
        for (int j = 0; j < 8; ++j)
            #pragma unroll
            for (int q = 0; q < 4; ++q) acc[i][j][q] = 0.f;

    issue(0);
    issue(1);

    #pragma unroll 1
    for (int t = 0; t < 8; ++t) {
        if (t < 7) cp_wait1(); else cp_wait0();
        __syncthreads();
        if (t + 2 < 8) issue(t + 2);

        const int buf = t % 3;
        const uint32_t sA = sb + buf * LNG_STAGE;
        const uint32_t sB = sA + 8192;

        #pragma unroll
        for (int q = 0; q < 4; ++q) {
            const int kc = 2 * q;
            uint32_t af[2][4], bf[4][4];
            #pragma unroll
            for (int i = 0; i < 2; ++i)
                ldsm4(af[i], sA + (uint32_t)(a_row_base + i * 16) * 128 +
                              (uint32_t)(((kc + a_cc_add) ^ l7) << 4));
            #pragma unroll
            for (int j2 = 0; j2 < 4; ++j2)
                ldsm4(bf[j2], sB + (uint32_t)(b_row_base + j2 * 16) * 128 +
                               (uint32_t)(((kc + b_cc_add) ^ l7) << 4));
            #pragma unroll
            for (int i = 0; i < 2; ++i)
                #pragma unroll
                for (int j = 0; j < 8; ++j)
                    mma_f16(acc[i][j], af[i], &bf[j >> 1][(j & 1) * 2]);
        }
    }
    __syncthreads();

    float2* red  = (float2*)smem;
    float2* stat = (float2*)(smem + 4096);
    const int rq = lane >> 2;
    const int cq = (lane & 3) * 2;

    #pragma unroll
    for (int i = 0; i < 2; ++i) {
        #pragma unroll
        for (int h2 = 0; h2 < 2; ++h2) {
            int row_local = warp_m + i * 16 + h2 * 8 + rq;
            size_t grow = (rowBlk + row_local) * 512;
            float s = 0.f, ss = 0.f;
            #pragma unroll
            for (int j = 0; j < 8; ++j) {
                int col = warp_n + cq + j * 8;
                float2 sv = *(const float2*)(resid + grow + col);
                float v0 = acc[i][j][h2 * 2 + 0] + bias[col]     + sv.x;
                float v1 = acc[i][j][h2 * 2 + 1] + bias[col + 1] + sv.y;
                acc[i][j][h2 * 2 + 0] = v0;
                acc[i][j][h2 * 2 + 1] = v1;
                s += v0 + v1;
                ss = fmaf(v0, v0, ss); ss = fmaf(v1, v1, ss);
            }
            s  += __shfl_xor_sync(0xffffffffu, s, 1);  s  += __shfl_xor_sync(0xffffffffu, s, 2);
            ss += __shfl_xor_sync(0xffffffffu, ss, 1); ss += __shfl_xor_sync(0xffffffffu, ss, 2);
            if ((lane & 3) == 0) red[row_local * 8 + wid_n] = make_float2(s, ss);
        }
    }
    __syncthreads();
    if (tid < 64) {
        float s = 0.f, ss = 0.f;
        #pragma unroll
        for (int w = 0; w < 8; ++w) {
            float2 v = red[tid * 8 + w];
            s += v.x; ss += v.y;
        }
        float mean = s * (1.0f / 512.0f);
        float var  = ss * (1.0f / 512.0f) - mean * mean;
        stat[tid] = make_float2(mean, rsqrtf(var + 1e-5f));
    }
    __syncthreads();
    #pragma unroll
    for (int i = 0; i < 2; ++i) {
        #pragma unroll
        for (int h2 = 0; h2 < 2; ++h2) {
            int row_local = warp_m + i * 16 + h2 * 8 + rq;
            float2 st = stat[row_local];
            size_t grow = (rowBlk + row_local) * 512;
            #pragma unroll
            for (int j = 0; j < 8; ++j) {
                int col = warp_n + cq + j * 8;
                float y0 = (acc[i][j][h2 * 2 + 0] - st.x) * st.y * gam[col]     + bet[col];
                float y1 = (acc[i][j][h2 * 2 + 1] - st.x) * st.y * gam[col + 1] + bet[col + 1];
                *(__half2*)(outp + grow + col) = __floats2half2_rn(y0, y1);
            }
        }
    }
}

// ===== LNG2 fused with GCN premix: out = LN2(x + [A_jj x_j ; Σ A_jk x_k] @ Wcat + b)
// BM=64, BN=512, K=1024 (16 chunks). A operand GENERATED in smem:
//   t<8 : adiag-scaled x (uint4 load, fp32 scale, swizzled store)
//   t>=8: 17-tap mix from a staged x slice (<=85 rows, stride-33 words)
#define G2_BSTAGE 65536
#define G2_A_OFF  (3 * G2_BSTAGE)           // 196608: A tile (8192 B)
#define G2_XS_OFF (G2_A_OFF + 8192)         // staging uint32[85*33] = 11220 B
#define G2_AM_OFF (G2_XS_OFF + 11232)       // Amat float[17*18] = 1224 B
#define G2_SMEM   (G2_AM_OFF + 1248)        // 217280 B

__global__ __launch_bounds__(512) void gcn_ln_gemm(const __half* __restrict__ x,
                                                   const __half* __restrict__ Bt,
                                                   const float* __restrict__ bias,
                                                   const float* __restrict__ gam,
                                                   const float* __restrict__ bet,
                                                   float* __restrict__ outp) {
    extern __shared__ char smem[];
    const uint32_t sb = smem_u32(smem);
    float* Amat = (float*)(smem + G2_AM_OFF);
    uint32_t* xs = (uint32_t*)(smem + G2_XS_OFF);
    const int tid  = threadIdx.x;
    const int lane = tid & 31;
    const int wid  = tid >> 5;
    const int warp_m = (wid & 1) * 32;
    const int wid_n  = wid >> 1;
    const int warp_n = wid_n * 64;
    const int l7 = lane & 7;
    const int a_row_base = warp_m + l7 + ((lane & 8) ? 8 : 0);
    const int a_cc_add = (lane & 16) ? 1 : 0;
    const int b_row_base = warp_n + l7 + ((lane & 16) ? 8 : 0);
    const int b_cc_add = (lane & 8) ? 1 : 0;

    const size_t rowBlk = (size_t)blockIdx.x * 64;
    const int bstart = (int)(rowBlk / 17);
    const int nrows  = ((int)(rowBlk + 63) / 17 - bstart) * 17 + 17;   // <= 85

    if (tid < NJ * NJ) Amat[(tid / NJ) * 18 + (tid % NJ)] = g_A[tid];

    // per-thread A-generation indices (thread -> one 16B output of the 64x64 tile)
    const int ar  = tid >> 3;            // 0..63 local row
    const int ac8 = tid & 7;             // 0..7  16B chunk
    const int ag  = (int)rowBlk + ar;    // global row
    const int ab  = ag / 17;
    const int aj  = ag - ab * 17;        // joint index
    const int asrc = (ab - bstart) * 17; // staging row base for this batch
    const uint32_t a_sw = (uint32_t)(ar * 128 + ((ac8 ^ (ar & 7)) << 4));

    auto issueB = [&](int t) {
        const int buf = t % 3;
        const uint32_t sB = sb + buf * G2_BSTAGE;
        const __half* Bb = Bt + t * 64;
        #pragma unroll
        for (int ll = 0; ll < 8; ++ll) {
            int id = tid + ll * 512, row = id >> 3, cc = id & 7;
            cp16(sB + row * 128 + ((cc ^ (row & 7)) << 4), Bb + (size_t)row * 1024 + cc * 8);
        }
        cp_commit();
    };

    float acc[2][8][4];
    #pragma unroll
    for (int i = 0; i < 2; ++i)
        #pragma unroll
        for (int j = 0; j < 8; ++j)
            #pragma unroll
            for (int q = 0; q < 4; ++q) acc[i][j][q] = 0.f;

    issueB(0);
    issueB(1);

    #pragma unroll 1
    for (int t = 0; t < 16; ++t) {
        if (t < 15) cp_wait1(); else cp_wait0();
        __syncthreads();                       // B reuse, sA reuse, xs reuse, Amat ready
        if (t + 2 < 16) issueB(t + 2);

        if (t < 8) {
            // A tile = A_jj * x rows, column slice t*64
            const float ad = Amat[aj * 18 + aj];
            uint4 w = *(const uint4*)(x + (size_t)ag * 512 + t * 64 + ac8 * 8);
            uint32_t r[4] = {w.x, w.y, w.z, w.w};
            #pragma unroll
            for (int q = 0; q < 4; ++q) {
                float2 f = __half22float2(*(__half2*)&r[q]);
                __half2 h = __floats2half2_rn(f.x * ad, f.y * ad);
                r[q] = *(uint32_t*)&h;
            }
            *(uint4*)(smem + G2_A_OFF + a_sw) = make_uint4(r[0], r[1], r[2], r[3]);
        } else {
            // stage x slice: nrows x 64 halves, column slice (t-8)*64
            const int cb = (t - 8) * 64;
            for (int i = tid; i < nrows * 8; i += 512) {
                int rr = i >> 3, c8 = i & 7;
                uint4 w = *(const uint4*)(x + (size_t)(bstart * 17 + rr) * 512 + cb + c8 * 8);
                uint32_t* d = xs + rr * 33 + c8 * 4;
                d[0] = w.x; d[1] = w.y; d[2] = w.z; d[3] = w.w;
            }
            __syncthreads();
            // mix: out[ar][ac8*8..+7] = sum_k A[aj][k] * xs[asrc+k][..]
            float a8[8];
            #pragma unroll
            for (int q = 0; q < 8; ++q) a8[q] = 0.f;
            #pragma unroll
            for (int k = 0; k < NJ; ++k) {
                float a = Amat[aj * 18 + k];
                const uint32_t* s = xs + (asrc + k) * 33 + ac8 * 4;
                #pragma unroll
                for (int w2 = 0; w2 < 4; ++w2) {
                    float2 f = __half22float2(*(const __half2*)&s[w2]);
                    a8[2 * w2]     = fmaf(a, f.x, a8[2 * w2]);
                    a8[2 * w2 + 1] = fmaf(a, f.y, a8[2 * w2 + 1]);
                }
            }
            uint32_t r[4];
            #pragma unroll
            for (int q = 0; q < 4; ++q) {
                __half2 h = __floats2half2_rn(a8[2 * q], a8[2 * q + 1]);
                r[q] = *(uint32_t*)&h;
            }
            *(uint4*)(smem + G2_A_OFF + a_sw) = make_uint4(r[0], r[1], r[2], r[3]);
        }
        __syncthreads();                       // A tile visible

        const uint32_t sA = sb + G2_A_OFF;
        const uint32_t sB = sb + (t % 3) * G2_BSTAGE;
        #pragma unroll
        for (int q = 0; q < 4; ++q) {
            const int kc = 2 * q;
            uint32_t af[2][4], bf[4][4];
            #pragma unroll
            for (int i = 0; i < 2; ++i)
                ldsm4(af[i], sA + (uint32_t)(a_row_base + i * 16) * 128 +
                              (uint32_t)(((kc + a_cc_add) ^ l7) << 4));
            #pragma unroll
            for (int j2 = 0; j2 < 4; ++j2)
                ldsm4(bf[j2], sB + (uint32_t)(b_row_base + j2 * 16) * 128 +
                               (uint32_t)(((kc + b_cc_add) ^ l7) << 4));
            #pragma unroll
            for (int i = 0; i < 2; ++i)
                #pragma unroll
                for (int j = 0; j < 8; ++j)
                    mma_f16(acc[i][j], af[i], &bf[j >> 1][(j & 1) * 2]);
        }
    }
    __syncthreads();

    // epilogue: v = acc + bias + x (half residual); LN2 over full row; fp32 out
    float2* red  = (float2*)smem;
    float2* stat = (float2*)(smem + 4096);
    const int rq = lane >> 2;
    const int cq = (lane & 3) * 2;

    #pragma unroll
    for (int i = 0; i < 2; ++i) {
        #pragma unroll
        for (int h2 = 0; h2 < 2; ++h2) {
            int row_local = warp_m + i * 16 + h2 * 8 + rq;
            size_t grow = (rowBlk + row_local) * 512;
            float s = 0.f, ss = 0.f;
            #pragma unroll
            for (int j = 0; j < 8; ++j) {
                int col = warp_n + cq + j * 8;
                float2 sv = __half22float2(*(const __half2*)(x + grow + col));
                float v0 = acc[i][j][h2 * 2 + 0] + bias[col]     + sv.x;
                float v1 = acc[i][j][h2 * 2 + 1] + bias[col + 1] + sv.y;
                acc[i][j][h2 * 2 + 0] = v0;
                acc[i][j][h2 * 2 + 1] = v1;
                s += v0 + v1;
                ss = fmaf(v0, v0, ss); ss = fmaf(v1, v1, ss);
            }
            s  += __shfl_xor_sync(0xffffffffu, s, 1);  s  += __shfl_xor_sync(0xffffffffu, s, 2);
            ss += __shfl_xor_sync(0xffffffffu, ss, 1); ss += __shfl_xor_sync(0xffffffffu, ss, 2);
            if ((lane & 3) == 0) red[row_local * 8 + wid_n] = make_float2(s, ss);
        }
    }
    __syncthreads();
    if (tid < 64) {
        float s = 0.f, ss = 0.f;
        #pragma unroll
        for (int w = 0; w < 8; ++w) {
            float2 v = red[tid * 8 + w];
            s += v.x; ss += v.y;
        }
        float mean = s * (1.0f / 512.0f);
        float var  = ss * (1.0f / 512.0f) - mean * mean;
        stat[tid] = make_float2(mean, rsqrtf(var + 1e-5f));
    }
    __syncthreads();
    #pragma unroll
    for (int i = 0; i < 2; ++i) {
        #pragma unroll
        for (int h2 = 0; h2 < 2; ++h2) {
            int row_local = warp_m + i * 16 + h2 * 8 + rq;
            float2 st = stat[row_local];
            size_t grow = (rowBlk + row_local) * 512;
            #pragma unroll
            for (int j = 0; j < 8; ++j) {
                int col = warp_n + cq + j * 8;
                float y0 = (acc[i][j][h2 * 2 + 0] - st.x) * st.y * gam[col]     + bet[col];
                float y1 = (acc[i][j][h2 * 2 + 1] - st.x) * st.y * gam[col + 1] + bet[col + 1];
                *(float2*)(outp + grow + col) = make_float2(y0, y1);
            }
        }
    }
}

// ---------------- src -> half (float4 per thread) -------------------------------
__global__ void conv_src(const float* __restrict__ src) {
    size_t idx = (size_t)blockIdx.x * blockDim.x + threadIdx.x;
    if (idx >= (size_t)BJ * 128) return;
    float4 v = *(const float4*)(src + idx * 4);
    __half2 a = __floats2half2_rn(v.x, v.y);
    __half2 b = __floats2half2_rn(v.z, v.w);
    uint2 w;
    w.x = *(uint32_t*)&a;
    w.y = *(uint32_t*)&b;
    *(uint2*)(g_src_h + idx * 4) = w;
}

// ---------------- weight packing (transpose to [N][K], half) --------------------
__global__ void pack_qkv_w(const float* __restrict__ Wq, const float* __restrict__ Wk,
                           const float* __restrict__ Wv, const float* __restrict__ bq,
                           const float* __restrict__ bk, const float* __restrict__ bv) {
    int idx = blockIdx.x * blockDim.x + threadIdx.x;
    if (idx >= 512 * 1536) return;
    int d = idx / 1536, cc2 = idx % 1536;
    int sel = cc2 / 512, cc = cc2 % 512;
    int h = cc / 64, e = cc % 64;
    const float* W = (sel == 0) ? Wq : (sel == 1) ? Wk : Wv;   // [H, D, DK]
    g_Wqkv[(size_t)cc2 * 512 + d] = __float2half_rn(W[((size_t)h * 512 + d) * 64 + e]);
    if (d == 0) {
        const float* bb = (sel == 0) ? bq : (sel == 1) ? bk : bv;
        g_bqkv[cc2] = bb[cc];
    }
}

__global__ void pack_wo(const float* __restrict__ Wo) {  // [512,512] -> [N][K]
    int idx = blockIdx.x * blockDim.x + threadIdx.x;
    if (idx >= 512 * 512) return;
    int n = idx / 512, k = idx % 512;
    g_Wo_t[idx] = __float2half_rn(Wo[(size_t)k * 512 + n]);
}

// W_cat[n][k]: k<512 -> (W0-W1)[k][n]; k>=512 -> W1[k-512][n]
__global__ void pack_wcat(const float* __restrict__ Wgcn) {
    int idx = blockIdx.x * blockDim.x + threadIdx.x;
    if (idx >= 512 * 1024) return;
    int n = idx / 1024, k = idx % 1024;
    float v;
    if (k < 512) v = Wgcn[(size_t)k * 512 + n] - Wgcn[262144 + (size_t)k * 512 + n];
    else         v = Wgcn[262144 + (size_t)(k - 512) * 512 + n];
    g_Wcat[idx] = __float2half_rn(v);
}

// ---------------- adjacency softmax ---------------------------------------------
__global__ void build_A(const int* __restrict__ rows, const int* __restrict__ cols,
                        const float* __restrict__ e, int nnz) {
    __shared__ float lg[NJ][NJ];
    int tid = threadIdx.x;
    if (tid < NJ * NJ) lg[tid / NJ][tid % NJ] = -9e15f;
    __syncthreads();
    if (tid < nnz) lg[rows[tid]][cols[tid]] = e[tid];
    __syncthreads();
    if (tid < NJ) {
        float m = -9e15f;
        #pragma unroll
        for (int k = 0; k < NJ; k++) m = fmaxf(m, lg[tid][k]);
        float ex[NJ]; float s = 0.f;
        #pragma unroll
        for (int k = 0; k < NJ; k++) { ex[k] = __expf(lg[tid][k] - m); s += ex[k]; }
        float inv = 1.0f / s;
        #pragma unroll
        for (int k = 0; k < NJ; k++) g_A[tid * NJ + k] = ex[k] * inv;
    }
}

// ---------------- attention: one block per batch b, 9 warps, half2 smem ---------
#define QLD 257
#define KLD 259
#define VLD 257
#define ATTN_SMEM (NJ * (QLD + KLD + VLD) * 4)

__global__ __launch_bounds__(288) void attn_kernel(const __half* __restrict__ qkv,
                                                   __half* __restrict__ o) {
    extern __shared__ uint32_t sm2[];
    uint32_t* qs = sm2;
    uint32_t* ks = qs + NJ * QLD;
    uint32_t* vs = ks + NJ * KLD;

    int b = blockIdx.x;
    int tid = threadIdx.x;
    const uint32_t* base = (const uint32_t*)(qkv + (size_t)b * NJ * 1536);

    for (int i = tid; i < NJ * 768; i += 288) {
        int row = i / 768, c = i % 768;
        uint32_t w = base[row * 768 + c];
        if (c < 256)      qs[row * QLD + c]        = w;
        else if (c < 512) ks[row * KLD + (c - 256)] = w;
        else              vs[row * VLD + (c - 512)] = w;
    }
    __syncthreads();

    int wrp = tid >> 5, lane = tid & 31;
    #pragma unroll 1
    for (int rep = 0; rep < 2; ++rep) {
        int j = wrp + rep * 9;
        if (j >= NJ) break;
        __half* orow = o + ((size_t)(b * NJ + j)) * 512;

        #pragma unroll 1
        for (int h = 0; h < NH; ++h) {
            const int hw = h * 32;
            float s = -1e30f;
            if (lane < NJ) {
                const uint32_t* qp = qs + j * QLD + hw;
                const uint32_t* kp = ks + lane * KLD + hw;
                float acc = 0.f;
                #pragma unroll
                for (int e = 0; e < 32; ++e) {
                    float2 qv = __half22float2(*(const __half2*)&qp[e]);
                    float2 kv = __half22float2(*(const __half2*)&kp[e]);
                    acc = fmaf(qv.x, kv.x, fmaf(qv.y, kv.y, acc));
                }
                s = acc * 0.125f;
            }
            float m = s;
            #pragma unroll
            for (int off = 16; off; off >>= 1) m = fmaxf(m, __shfl_xor_sync(0xffffffffu, m, off));
            float p = (lane < NJ) ? __expf(s - m) : 0.f;
            float sum = p;
            #pragma unroll
            for (int off = 16; off; off >>= 1) sum += __shfl_xor_sync(0xffffffffu, sum, off);
            p *= (1.0f / sum);

            const int wsel = lane & 1;
            const int widx = hw + (lane >> 1);
            float o0 = 0.f, o1 = 0.f;
            #pragma unroll
            for (int k = 0; k < NJ; ++k) {
                float pk = __shfl_sync(0xffffffffu, p, k);
                __half2 w0 = *(__half2*)&vs[k * VLD + widx];
                __half2 w1 = *(__half2*)&vs[k * VLD + widx + 16];
                float v0 = wsel ? __high2float(w0) : __low2float(w0);
                float v1 = wsel ? __high2float(w1) : __low2float(w1);
                o0 = fmaf(pk, v0, o0);
                o1 = fmaf(pk, v1, o1);
            }
            orow[h * 64 + lane]      = __float2half_rn(o0);
            orow[h * 64 + lane + 32] = __float2half_rn(o1);
        }
    }
}

// ---------------- host launcher --------------------------------------------------
extern "C" void kernel_launch(void* const* d_in, const int* in_sizes, int n_in,
                              void* d_out, int out_size) {
    const float* src   = (const float*)d_in[0];
    const float* Wq    = (const float*)d_in[1];
    const float* bq    = (const float*)d_in[2];
    const float* Wk    = (const float*)d_in[3];
    const float* bk    = (const float*)d_in[4];
    const float* Wv    = (const float*)d_in[5];
    const float* bv    = (const float*)d_in[6];
    const float* Wo    = (const float*)d_in[7];
    const float* bo    = (const float*)d_in[8];
    const float* ln1_g = (const float*)d_in[9];
    const float* ln1_b = (const float*)d_in[10];
    const float* Wgcn  = (const float*)d_in[11];
    const float* egcn  = (const float*)d_in[12];
    const float* bgcn  = (const float*)d_in[13];
    const float* ln2_g = (const float*)d_in[14];
    const float* ln2_b = (const float*)d_in[15];
    const int*   mrows = (const int*)d_in[16];
    const int*   mcols = (const int*)d_in[17];
    int nnz = in_sizes[16];
    float* out = (float*)d_out;

    __half *p_srch, *p_qkv, *p_o, *p_xh, *p_Wqkv, *p_Wot, *p_Wcat;
    float *p_bqkv;
    cudaGetSymbolAddress((void**)&p_srch, g_src_h);
    cudaGetSymbolAddress((void**)&p_qkv,  g_qkv);
    cudaGetSymbolAddress((void**)&p_o,    g_o);
    cudaGetSymbolAddress((void**)&p_xh,   g_x_h);
    cudaGetSymbolAddress((void**)&p_Wqkv, g_Wqkv);
    cudaGetSymbolAddress((void**)&p_bqkv, g_bqkv);
    cudaGetSymbolAddress((void**)&p_Wot,  g_Wo_t);
    cudaGetSymbolAddress((void**)&p_Wcat, g_Wcat);

    static cudaStream_t s_side = nullptr, s_side2 = nullptr;
    static cudaEvent_t e_fork = nullptr, e_join = nullptr, e_join2 = nullptr;
    if (!s_side) {
        cudaStreamCreateWithFlags(&s_side, cudaStreamNonBlocking);
        cudaStreamCreateWithFlags(&s_side2, cudaStreamNonBlocking);
        cudaEventCreateWithFlags(&e_fork, cudaEventDisableTiming);
        cudaEventCreateWithFlags(&e_join, cudaEventDisableTiming);
        cudaEventCreateWithFlags(&e_join2, cudaEventDisableTiming);
        cudaFuncSetAttribute(tc_gemm, cudaFuncAttributeMaxDynamicSharedMemorySize, GEMM_SMEM);
        cudaFuncSetAttribute(ln_gemm1, cudaFuncAttributeMaxDynamicSharedMemorySize, LNG_SMEM);
        cudaFuncSetAttribute(gcn_ln_gemm, cudaFuncAttributeMaxDynamicSharedMemorySize, G2_SMEM);
        cudaFuncSetAttribute(attn_kernel, cudaFuncAttributeMaxDynamicSharedMemorySize, ATTN_SMEM);
    }

    // fork: side branch 1 packs weights needed from ln_gemm1 onward
    cudaEventRecord(e_fork, 0);
    cudaStreamWaitEvent(s_side, e_fork, 0);
    cudaStreamWaitEvent(s_side2, e_fork, 0);
    pack_wo<<<(512 * 512 + 255) / 256, 256, 0, s_side>>>(Wo);
    pack_wcat<<<(512 * 1024 + 255) / 256, 256, 0, s_side>>>(Wgcn);
    build_A<<<1, 512, 0, s_side>>>(mrows, mcols, egcn, nnz);
    cudaEventRecord(e_join, s_side);

    // side branch 2: QKV weight pack (parallel with conv_src)
    pack_qkv_w<<<(512 * 1536 + 255) / 256, 256, 0, s_side2>>>(Wq, Wk, Wv, bq, bk, bv);
    cudaEventRecord(e_join2, s_side2);

    // main branch
    conv_src<<<(BJ * 128 + 255) / 256, 256>>>(src);
    cudaStreamWaitEvent(0, e_join2, 0);

    // fused QKV GEMM: [BJ,512] @ [512,1536] -> half
    tc_gemm<<<dim3(1536 / 128, BJ / 128), 256, GEMM_SMEM>>>(p_srch, p_Wqkv, p_bqkv, p_qkv, 1536);

    // attention
    attn_kernel<<<NB, 288, ATTN_SMEM>>>(p_qkv, p_o);

    // join side branch 1
    cudaStreamWaitEvent(0, e_join, 0);

    // fused: x = LN1(src + o @ Wo + bo) -> half
    ln_gemm1<<<BJ / 64, 512, LNG_SMEM>>>(p_o, p_Wot, bo, src, ln1_g, ln1_b, p_xh);

    // fused GCN premix + GEMM + LN2 -> out (fp32)
    gcn_ln_gemm<<<BJ / 64, 512, G2_SMEM>>>(p_xh, p_Wcat, bgcn, ln2_g, ln2_b, out);
}

// round 11
// speedup vs baseline: 1.0424x; 1.0424x over previous
#include <cuda_runtime.h>
#include <cuda_fp16.h>
#include <cstdint>
#include <cstddef>

// Problem constants
#define BJ   69632           // 4096*17 rows
#define NB   4096
#define NJ   17
#define ND   512
#define NH   8
#define NDK  64

// ---------------- device scratch ------------------------------------------------
__device__ __half g_src_h[(size_t)BJ * 512];   // src as half
__device__ __half g_qkv  [(size_t)BJ * 1536];  // fused Q|K|V (half)
__device__ __half g_o    [(size_t)BJ * 512];   // attention output (half)
__device__ __half g_x_h  [(size_t)BJ * 512];   // LN1 output (half)
__device__ __half g_u    [(size_t)BJ * 1024];  // premixed GCN input (half)
__device__ __half g_Wqkv[1536 * 512];          // transposed [N][K] half
__device__ float  g_bqkv[1536];
__device__ __half g_Wo_t[512 * 512];           // transposed [N][K] half
__device__ __half g_Wcat[512 * 1024];          // [N=512][K=1024]: [W0-W1 ; W1]^T half
__device__ float  g_A[NJ * NJ];

// ---------------- helpers -------------------------------------------------------
__device__ __forceinline__ uint32_t smem_u32(const void* p) {
    uint32_t a;
    asm("{ .reg .u64 t; cvta.to.shared.u64 t, %1; cvt.u32.u64 %0, t; }" : "=r"(a) : "l"(p));
    return a;
}
__device__ __forceinline__ void cp16(uint32_t saddr, const void* gptr) {
    asm volatile("cp.async.cg.shared.global [%0], [%1], 16;" :: "r"(saddr), "l"(gptr));
}
__device__ __forceinline__ void cp_commit() { asm volatile("cp.async.commit_group;" ::: "memory"); }
__device__ __forceinline__ void cp_wait1()  { asm volatile("cp.async.wait_group 1;" ::: "memory"); }
__device__ __forceinline__ void cp_wait0()  { asm volatile("cp.async.wait_group 0;" ::: "memory"); }

__device__ __forceinline__ void ldsm4(uint32_t* r, uint32_t addr) {
    asm volatile("ldmatrix.sync.aligned.m8n8.x4.shared.b16 {%0,%1,%2,%3}, [%4];"
        : "=r"(r[0]), "=r"(r[1]), "=r"(r[2]), "=r"(r[3]) : "r"(addr));
}
__device__ __forceinline__ void mma_f16(float* d, const uint32_t* a, const uint32_t* b) {
    asm volatile(
        "mma.sync.aligned.m16n8k16.row.col.f32.f16.f16.f32 "
        "{%0,%1,%2,%3}, {%4,%5,%6,%7}, {%8,%9}, {%0,%1,%2,%3};"
        : "+f"(d[0]), "+f"(d[1]), "+f"(d[2]), "+f"(d[3])
        : "r"(a[0]), "r"(a[1]), "r"(a[2]), "r"(a[3]), "r"(b[0]), "r"(b[1]));
}

// ================= fp16 mma.sync GEMM: C[M,N] = A[M,512] @ Bt[N,512]^T (+bias) ==
// Tile: BM=128, BN=128, BK=64 halves, 256 threads (8 warps 2x4), warp tile 64x32.
// 3 stages x 32KB = 96KB smem -> 2 CTAs/SM (16 warps resident).
#define STAGE_BYTES 32768     // A: 128*128B=16KB, B: 128*128B=16KB
#define GEMM_SMEM   (3 * STAGE_BYTES)

__global__ __launch_bounds__(256, 2) void tc_gemm(const __half* __restrict__ A,
                                                  const __half* __restrict__ Bt,
                                                  const float* __restrict__ bias,
                                                  __half* __restrict__ C, int N) {
    extern __shared__ char smem[];
    const uint32_t sb = smem_u32(smem);
    const int tid  = threadIdx.x;
    const int lane = tid & 31;
    const int wid  = tid >> 5;
    const int warp_m = (wid & 1) * 64;
    const int warp_n = (wid >> 1) * 32;
    const int l7 = lane & 7;
    const int a_row_base = warp_m + l7 + ((lane & 8) ? 8 : 0);
    const int a_cc_add = (lane & 16) ? 1 : 0;
    const int b_row_base = warp_n + l7 + ((lane & 16) ? 8 : 0);
    const int b_cc_add = (lane & 8) ? 1 : 0;

    const __half* Abase = A  + (size_t)blockIdx.y * 128 * 512;
    const __half* Bbase = Bt + (size_t)blockIdx.x * 128 * 512;

    auto issue = [&](int t) {
        const int buf = t % 3;
        const uint32_t sA = sb + buf * STAGE_BYTES;
        const uint32_t sB = sA + 16384;
        const __half* Ab = Abase + t * 64;
        const __half* Bb = Bbase + t * 64;
        #pragma unroll
        for (int ll = 0; ll < 4; ++ll) {
            int id = tid + ll * 256, row = id >> 3, cc = id & 7;
            cp16(sA + row * 128 + ((cc ^ (row & 7)) << 4), Ab + (size_t)row * 512 + cc * 8);
        }
        #pragma unroll
        for (int ll = 0; ll < 4; ++ll) {
            int id = tid + ll * 256, row = id >> 3, cc = id & 7;
            cp16(sB + row * 128 + ((cc ^ (row & 7)) << 4), Bb + (size_t)row * 512 + cc * 8);
        }
        cp_commit();
    };

    float acc[4][4][4];
    #pragma unroll
    for (int i = 0; i < 4; ++i)
        #pragma unroll
        for (int j = 0; j < 4; ++j)
            #pragma unroll
            for (int q = 0; q < 4; ++q) acc[i][j][q] = 0.f;

    issue(0);
    issue(1);

    #pragma unroll 1
    for (int t = 0; t < 8; ++t) {
        if (t < 7) cp_wait1(); else cp_wait0();
        __syncthreads();
        if (t + 2 < 8) issue(t + 2);

        const int buf = t % 3;
        const uint32_t sA = sb + buf * STAGE_BYTES;
        const uint32_t sB = sA + 16384;

        #pragma unroll
        for (int q = 0; q < 4; ++q) {
            const int kc = 2 * q;
            uint32_t af[4][4], bf[2][4];
            #pragma unroll
            for (int i = 0; i < 4; ++i)
                ldsm4(af[i], sA + (uint32_t)(a_row_base + i * 16) * 128 +
                              (uint32_t)(((kc + a_cc_add) ^ l7) << 4));
            #pragma unroll
            for (int j2 = 0; j2 < 2; ++j2)
                ldsm4(bf[j2], sB + (uint32_t)(b_row_base + j2 * 16) * 128 +
                               (uint32_t)(((kc + b_cc_add) ^ l7) << 4));
            #pragma unroll
            for (int i = 0; i < 4; ++i)
                #pragma unroll
                for (int j = 0; j < 4; ++j)
                    mma_f16(acc[i][j], af[i], &bf[j >> 1][(j & 1) * 2]);
        }
    }

    // epilogue (registers only)
    const size_t rowBase = (size_t)blockIdx.y * 128 + warp_m + (lane >> 2);
    const int colBase = blockIdx.x * 128 + warp_n + (lane & 3) * 2;
    #pragma unroll
    for (int i = 0; i < 4; ++i) {
        #pragma unroll
        for (int j = 0; j < 4; ++j) {
            size_t m0 = rowBase + i * 16;
            int n0 = colBase + j * 8;
            float b0 = bias[n0], b1 = bias[n0 + 1];
            *(__half2*)(C + m0 * (size_t)N + n0) =
                __floats2half2_rn(acc[i][j][0] + b0, acc[i][j][1] + b1);
            *(__half2*)(C + (m0 + 8) * (size_t)N + n0) =
                __floats2half2_rn(acc[i][j][2] + b0, acc[i][j][3] + b1);
        }
    }
}

// ===== fused GEMM + bias + residual + LayerNorm (full 512-wide rows) ============
// BM=64, BN=512, BK=64, 512 threads (16 warps 2x8), warp tile 32x64.
#define LNG_STAGE (8192 + 65536)      // A: 64*128B, B: 512*128B
#define LNG_SMEM  (3 * LNG_STAGE)

template<int NCHUNK, bool RES_HALF, bool OUT_HALF>
__global__ __launch_bounds__(512) void ln_gemm_t(const __half* __restrict__ A,
                                                 const __half* __restrict__ Bt,
                                                 const float* __restrict__ bias,
                                                 const void* __restrict__ resid,
                                                 const float* __restrict__ gam,
                                                 const float* __restrict__ bet,
                                                 void* __restrict__ outp) {
    constexpr int K = NCHUNK * 64;
    extern __shared__ char smem[];
    const uint32_t sb = smem_u32(smem);
    const int tid  = threadIdx.x;
    const int lane = tid & 31;
    const int wid  = tid >> 5;          // 0..15
    const int warp_m = (wid & 1) * 32;  // 2 warp-rows of 32
    const int wid_n  = wid >> 1;        // 0..7
    const int warp_n = wid_n * 64;      // 8 warp-cols of 64
    const int l7 = lane & 7;
    const int a_row_base = warp_m + l7 + ((lane & 8) ? 8 : 0);
    const int a_cc_add = (lane & 16) ? 1 : 0;
    const int b_row_base = warp_n + l7 + ((lane & 16) ? 8 : 0);
    const int b_cc_add = (lane & 8) ? 1 : 0;

    const size_t rowBlk = (size_t)blockIdx.x * 64;
    const __half* Abase = A + rowBlk * K;

    auto issue = [&](int t) {
        const int buf = t % 3;
        const uint32_t sA = sb + buf * LNG_STAGE;
        const uint32_t sB = sA + 8192;
        const __half* Ab = Abase + t * 64;
        const __half* Bb = Bt + t * 64;
        {
            int row = tid >> 3, cc = tid & 7;
            cp16(sA + row * 128 + ((cc ^ (row & 7)) << 4), Ab + (size_t)row * K + cc * 8);
        }
        #pragma unroll
        for (int ll = 0; ll < 8; ++ll) {
            int id = tid + ll * 512, row = id >> 3, cc = id & 7;
            cp16(sB + row * 128 + ((cc ^ (row & 7)) << 4), Bb + (size_t)row * K + cc * 8);
        }
        cp_commit();
    };

    float acc[2][8][4];
    #pragma unroll
    for (int i = 0; i < 2; ++i)
        #pragma unroll
        for (int j = 0; j < 8; ++j)
            #pragma unroll
            for (int q = 0; q < 4; ++q) acc[i][j][q] = 0.f;

    issue(0);
    issue(1);

    #pragma unroll 1
    for (int t = 0; t < NCHUNK; ++t) {
        if (t < NCHUNK - 1) cp_wait1(); else cp_wait0();
        __syncthreads();
        if (t + 2 < NCHUNK) issue(t + 2);

        const int buf = t % 3;
        const uint32_t sA = sb + buf * LNG_STAGE;
        const uint32_t sB = sA + 8192;

        #pragma unroll
        for (int q = 0; q < 4; ++q) {
            const int kc = 2 * q;
            uint32_t af[2][4], bf[4][4];
            #pragma unroll
            for (int i = 0; i < 2; ++i)
                ldsm4(af[i], sA + (uint32_t)(a_row_base + i * 16) * 128 +
                              (uint32_t)(((kc + a_cc_add) ^ l7) << 4));
            #pragma unroll
            for (int j2 = 0; j2 < 4; ++j2)
                ldsm4(bf[j2], sB + (uint32_t)(b_row_base + j2 * 16) * 128 +
                               (uint32_t)(((kc + b_cc_add) ^ l7) << 4));
            #pragma unroll
            for (int i = 0; i < 2; ++i)
                #pragma unroll
                for (int j = 0; j < 8; ++j)
                    mma_f16(acc[i][j], af[i], &bf[j >> 1][(j & 1) * 2]);
        }
    }
    __syncthreads();   // protect smem reuse below

    // ---- epilogue: v = acc + bias + resid; LN over full row (512 cols) ----
    float2* red  = (float2*)smem;          // [64 rows][8 warp-cols]
    float2* stat = (float2*)(smem + 4096); // [64 rows] (mean, inv)
    const int rq = lane >> 2;
    const int cq = (lane & 3) * 2;

    #pragma unroll
    for (int i = 0; i < 2; ++i) {
        #pragma unroll
        for (int h2 = 0; h2 < 2; ++h2) {
            int row_local = warp_m + i * 16 + h2 * 8 + rq;
            size_t grow = (rowBlk + row_local) * 512;
            float s = 0.f, ss = 0.f;
            #pragma unroll
            for (int j = 0; j < 8; ++j) {
                int col = warp_n + cq + j * 8;
                float2 sv;
                if (RES_HALF)
                    sv = __half22float2(*(const __half2*)((const __half*)resid + grow + col));
                else
                    sv = *(const float2*)((const float*)resid + grow + col);
                float v0 = acc[i][j][h2 * 2 + 0] + bias[col]     + sv.x;
                float v1 = acc[i][j][h2 * 2 + 1] + bias[col + 1] + sv.y;
                acc[i][j][h2 * 2 + 0] = v0;
                acc[i][j][h2 * 2 + 1] = v1;
                s += v0 + v1;
                ss = fmaf(v0, v0, ss); ss = fmaf(v1, v1, ss);
            }
            s  += __shfl_xor_sync(0xffffffffu, s, 1);  s  += __shfl_xor_sync(0xffffffffu, s, 2);
            ss += __shfl_xor_sync(0xffffffffu, ss, 1); ss += __shfl_xor_sync(0xffffffffu, ss, 2);
            if ((lane & 3) == 0) red[row_local * 8 + wid_n] = make_float2(s, ss);
        }
    }
    __syncthreads();
    if (tid < 64) {
        float s = 0.f, ss = 0.f;
        #pragma unroll
        for (int w = 0; w < 8; ++w) {
            float2 v = red[tid * 8 + w];
            s += v.x; ss += v.y;
        }
        float mean = s * (1.0f / 512.0f);
        float var  = ss * (1.0f / 512.0f) - mean * mean;
        stat[tid] = make_float2(mean, rsqrtf(var + 1e-5f));
    }
    __syncthreads();
    #pragma unroll
    for (int i = 0; i < 2; ++i) {
        #pragma unroll
        for (int h2 = 0; h2 < 2; ++h2) {
            int row_local = warp_m + i * 16 + h2 * 8 + rq;
            float2 st = stat[row_local];
            size_t grow = (rowBlk + row_local) * 512;
            #pragma unroll
            for (int j = 0; j < 8; ++j) {
                int col = warp_n + cq + j * 8;
                float y0 = (acc[i][j][h2 * 2 + 0] - st.x) * st.y * gam[col]     + bet[col];
                float y1 = (acc[i][j][h2 * 2 + 1] - st.x) * st.y * gam[col + 1] + bet[col + 1];
                if (OUT_HALF)
                    *(__half2*)((__half*)outp + grow + col) = __floats2half2_rn(y0, y1);
                else
                    *(float2*)((float*)outp + grow + col) = make_float2(y0, y1);
            }
        }
    }
}

// ---------------- src -> half (float4 per thread) -------------------------------
__global__ void conv_src(const float* __restrict__ src) {
    size_t idx = (size_t)blockIdx.x * blockDim.x + threadIdx.x;
    if (idx >= (size_t)BJ * 128) return;
    float4 v = *(const float4*)(src + idx * 4);
    __half2 a = __floats2half2_rn(v.x, v.y);
    __half2 b = __floats2half2_rn(v.z, v.w);
    uint2 w;
    w.x = *(uint32_t*)&a;
    w.y = *(uint32_t*)&b;
    *(uint2*)(g_src_h + idx * 4) = w;
}

// ---------------- weight packing (transpose to [N][K], half) --------------------
__global__ void pack_qkv_w(const float* __restrict__ Wq, const float* __restrict__ Wk,
                           const float* __restrict__ Wv, const float* __restrict__ bq,
                           const float* __restrict__ bk, const float* __restrict__ bv) {
    int idx = blockIdx.x * blockDim.x + threadIdx.x;
    if (idx >= 512 * 1536) return;
    int d = idx / 1536, cc2 = idx % 1536;
    int sel = cc2 / 512, cc = cc2 % 512;
    int h = cc / 64, e = cc % 64;
    const float* W = (sel == 0) ? Wq : (sel == 1) ? Wk : Wv;   // [H, D, DK]
    g_Wqkv[(size_t)cc2 * 512 + d] = __float2half_rn(W[((size_t)h * 512 + d) * 64 + e]);
    if (d == 0) {
        const float* bb = (sel == 0) ? bq : (sel == 1) ? bk : bv;
        g_bqkv[cc2] = bb[cc];
    }
}

__global__ void pack_wo(const float* __restrict__ Wo) {  // [512,512] -> [N][K]
    int idx = blockIdx.x * blockDim.x + threadIdx.x;
    if (idx >= 512 * 512) return;
    int n = idx / 512, k = idx % 512;
    g_Wo_t[idx] = __float2half_rn(Wo[(size_t)k * 512 + n]);
}

// W_cat[n][k]: k<512 -> (W0-W1)[k][n]; k>=512 -> W1[k-512][n]
__global__ void pack_wcat(const float* __restrict__ Wgcn) {
    int idx = blockIdx.x * blockDim.x + threadIdx.x;
    if (idx >= 512 * 1024) return;
    int n = idx / 1024, k = idx % 1024;
    float v;
    if (k < 512) v = Wgcn[(size_t)k * 512 + n] - Wgcn[262144 + (size_t)k * 512 + n];
    else         v = Wgcn[262144 + (size_t)(k - 512) * 512 + n];
    g_Wcat[idx] = __float2half_rn(v);
}

// ---------------- adjacency softmax ---------------------------------------------
__global__ void build_A(const int* __restrict__ rows, const int* __restrict__ cols,
                        const float* __restrict__ e, int nnz) {
    __shared__ float lg[NJ][NJ];
    int tid = threadIdx.x;
    if (tid < NJ * NJ) lg[tid / NJ][tid % NJ] = -9e15f;
    __syncthreads();
    if (tid < nnz) lg[rows[tid]][cols[tid]] = e[tid];
    __syncthreads();
    if (tid < NJ) {
        float m = -9e15f;
        #pragma unroll
        for (int k = 0; k < NJ; k++) m = fmaxf(m, lg[tid][k]);
        float ex[NJ]; float s = 0.f;
        #pragma unroll
        for (int k = 0; k < NJ; k++) { ex[k] = __expf(lg[tid][k] - m); s += ex[k]; }
        float inv = 1.0f / s;
        #pragma unroll
        for (int k = 0; k < NJ; k++) g_A[tid * NJ + k] = ex[k] * inv;
    }
}

// ---------------- attention: one block per batch b, 9 warps, half2 smem ---------
#define QLD 257
#define KLD 259
#define VLD 257
#define ATTN_SMEM (NJ * (QLD + KLD + VLD) * 4)

__global__ __launch_bounds__(288) void attn_kernel(const __half* __restrict__ qkv,
                                                   __half* __restrict__ o) {
    extern __shared__ uint32_t sm2[];
    uint32_t* qs = sm2;
    uint32_t* ks = qs + NJ * QLD;
    uint32_t* vs = ks + NJ * KLD;

    int b = blockIdx.x;
    int tid = threadIdx.x;
    const uint32_t* base = (const uint32_t*)(qkv + (size_t)b * NJ * 1536);

    for (int i = tid; i < NJ * 768; i += 288) {
        int row = i / 768, c = i % 768;
        uint32_t w = base[row * 768 + c];
        if (c < 256)      qs[row * QLD + c]        = w;
        else if (c < 512) ks[row * KLD + (c - 256)] = w;
        else              vs[row * VLD + (c - 512)] = w;
    }
    __syncthreads();

    int wrp = tid >> 5, lane = tid & 31;
    #pragma unroll 1
    for (int rep = 0; rep < 2; ++rep) {
        int j = wrp + rep * 9;
        if (j >= NJ) break;
        __half* orow = o + ((size_t)(b * NJ + j)) * 512;

        #pragma unroll 1
        for (int h = 0; h < NH; ++h) {
            const int hw = h * 32;
            float s = -1e30f;
            if (lane < NJ) {
                const uint32_t* qp = qs + j * QLD + hw;
                const uint32_t* kp = ks + lane * KLD + hw;
                float acc = 0.f;
                #pragma unroll
                for (int e = 0; e < 32; ++e) {
                    float2 qv = __half22float2(*(const __half2*)&qp[e]);
                    float2 kv = __half22float2(*(const __half2*)&kp[e]);
                    acc = fmaf(qv.x, kv.x, fmaf(qv.y, kv.y, acc));
                }
                s = acc * 0.125f;
            }
            float m = s;
            #pragma unroll
            for (int off = 16; off; off >>= 1) m = fmaxf(m, __shfl_xor_sync(0xffffffffu, m, off));
            float p = (lane < NJ) ? __expf(s - m) : 0.f;
            float sum = p;
            #pragma unroll
            for (int off = 16; off; off >>= 1) sum += __shfl_xor_sync(0xffffffffu, sum, off);
            p *= (1.0f / sum);

            const int wsel = lane & 1;
            const int widx = hw + (lane >> 1);
            float o0 = 0.f, o1 = 0.f;
            #pragma unroll
            for (int k = 0; k < NJ; ++k) {
                float pk = __shfl_sync(0xffffffffu, p, k);
                __half2 w0 = *(__half2*)&vs[k * VLD + widx];
                __half2 w1 = *(__half2*)&vs[k * VLD + widx + 16];
                float v0 = wsel ? __high2float(w0) : __low2float(w0);
                float v1 = wsel ? __high2float(w1) : __low2float(w1);
                o0 = fmaf(pk, v0, o0);
                o1 = fmaf(pk, v1, o1);
            }
            orow[h * 64 + lane]      = __float2half_rn(o0);
            orow[h * 64 + lane + 32] = __float2half_rn(o1);
        }
    }
}

// ---------------- premix: u_j = [A_jj*x_j ; sum_k A_jk*x_k] ---------------------
__global__ __launch_bounds__(544) void premix(const __half* __restrict__ x,
                                              __half* __restrict__ u) {
    int b = blockIdx.x;
    __shared__ float xs[NJ][512];
    __shared__ float Arow[NJ][NJ];
    __shared__ float Ad[NJ];
    int tid = threadIdx.y * 32 + threadIdx.x;
    for (int i = tid; i < NJ * 256; i += 544) {
        int k = i >> 8, e2 = i & 255;
        float2 v = __half22float2(*(const __half2*)(x + ((size_t)(b * NJ + k)) * 512 + e2 * 2));
        xs[k][e2 * 2] = v.x; xs[k][e2 * 2 + 1] = v.y;
    }
    if (tid < NJ * NJ) {
        int j = tid / NJ, k = tid % NJ;
        float a = g_A[tid];
        Arow[j][k] = a;
        if (j == k) Ad[j] = a;
    }
    __syncthreads();

    int j = threadIdx.y, lane = threadIdx.x;
    __half* ur = u + ((size_t)(b * NJ + j)) * 1024;
    float adiag = Ad[j];
    #pragma unroll
    for (int t = 0; t < 16; t++) {
        int d = lane + (t << 5);
        float z = 0.f;
        #pragma unroll
        for (int k = 0; k < NJ; k++) z = fmaf(Arow[j][k], xs[k][d], z);
        ur[d]       = __float2half_rn(adiag * xs[j][d]);
        ur[512 + d] = __float2half_rn(z);
    }
}

// ---------------- host launcher --------------------------------------------------
extern "C" void kernel_launch(void* const* d_in, const int* in_sizes, int n_in,
                              void* d_out, int out_size) {
    const float* src   = (const float*)d_in[0];
    const float* Wq    = (const float*)d_in[1];
    const float* bq    = (const float*)d_in[2];
    const float* Wk    = (const float*)d_in[3];
    const float* bk    = (const float*)d_in[4];
    const float* Wv    = (const float*)d_in[5];
    const float* bv    = (const float*)d_in[6];
    const float* Wo    = (const float*)d_in[7];
    const float* bo    = (const float*)d_in[8];
    const float* ln1_g = (const float*)d_in[9];
    const float* ln1_b = (const float*)d_in[10];
    const float* Wgcn  = (const float*)d_in[11];
    const float* egcn  = (const float*)d_in[12];
    const float* bgcn  = (const float*)d_in[13];
    const float* ln2_g = (const float*)d_in[14];
    const float* ln2_b = (const float*)d_in[15];
    const int*   mrows = (const int*)d_in[16];
    const int*   mcols = (const int*)d_in[17];
    int nnz = in_sizes[16];
    float* out = (float*)d_out;

    __half *p_srch, *p_qkv, *p_o, *p_xh, *p_u, *p_Wqkv, *p_Wot, *p_Wcat;
    float *p_bqkv;
    cudaGetSymbolAddress((void**)&p_srch, g_src_h);
    cudaGetSymbolAddress((void**)&p_qkv,  g_qkv);
    cudaGetSymbolAddress((void**)&p_o,    g_o);
    cudaGetSymbolAddress((void**)&p_xh,   g_x_h);
    cudaGetSymbolAddress((void**)&p_u,    g_u);
    cudaGetSymbolAddress((void**)&p_Wqkv, g_Wqkv);
    cudaGetSymbolAddress((void**)&p_bqkv, g_bqkv);
    cudaGetSymbolAddress((void**)&p_Wot,  g_Wo_t);
    cudaGetSymbolAddress((void**)&p_Wcat, g_Wcat);

    static cudaStream_t s_side = nullptr, s_side2 = nullptr;
    static cudaEvent_t e_fork = nullptr, e_join = nullptr, e_join2 = nullptr;
    if (!s_side) {
        cudaStreamCreateWithFlags(&s_side, cudaStreamNonBlocking);
        cudaStreamCreateWithFlags(&s_side2, cudaStreamNonBlocking);
        cudaEventCreateWithFlags(&e_fork, cudaEventDisableTiming);
        cudaEventCreateWithFlags(&e_join, cudaEventDisableTiming);
        cudaEventCreateWithFlags(&e_join2, cudaEventDisableTiming);
        cudaFuncSetAttribute(tc_gemm, cudaFuncAttributeMaxDynamicSharedMemorySize, GEMM_SMEM);
        cudaFuncSetAttribute(ln_gemm_t<8,  false, true >, cudaFuncAttributeMaxDynamicSharedMemorySize, LNG_SMEM);
        cudaFuncSetAttribute(ln_gemm_t<16, true,  false>, cudaFuncAttributeMaxDynamicSharedMemorySize, LNG_SMEM);
        cudaFuncSetAttribute(attn_kernel, cudaFuncAttributeMaxDynamicSharedMemorySize, ATTN_SMEM);
    }

    // ---- fork: side branch 1 packs weights not needed until ln_gemm1/premix/ln_gemm2
    cudaEventRecord(e_fork, 0);
    cudaStreamWaitEvent(s_side, e_fork, 0);
    cudaStreamWaitEvent(s_side2, e_fork, 0);
    pack_wo<<<(512 * 512 + 255) / 256, 256, 0, s_side>>>(Wo);
    pack_wcat<<<(512 * 1024 + 255) / 256, 256, 0, s_side>>>(Wgcn);
    build_A<<<1, 512, 0, s_side>>>(mrows, mcols, egcn, nnz);
    cudaEventRecord(e_join, s_side);

    // ---- side branch 2: QKV weight pack (parallel with conv_src)
    pack_qkv_w<<<(512 * 1536 + 255) / 256, 256, 0, s_side2>>>(Wq, Wk, Wv, bq, bk, bv);
    cudaEventRecord(e_join2, s_side2);

    // ---- main branch
    conv_src<<<(BJ * 128 + 255) / 256, 256>>>(src);
    cudaStreamWaitEvent(0, e_join2, 0);

    // fused QKV GEMM: [BJ,512] @ [512,1536] -> half
    tc_gemm<<<dim3(1536 / 128, BJ / 128), 256, GEMM_SMEM>>>(p_srch, p_Wqkv, p_bqkv, p_qkv, 1536);

    // attention (per-batch blocks, all heads, 9 warps x 2 queries)
    attn_kernel<<<NB, 288, ATTN_SMEM>>>(p_qkv, p_o);

    // ---- join side branch 1 before consumers of Wo_t / Wcat / A
    cudaStreamWaitEvent(0, e_join, 0);

    // fused: x = LN1(src + o @ Wo + bo) -> half
    ln_gemm_t<8, false, true><<<BJ / 64, 512, LNG_SMEM>>>(p_o, p_Wot, bo, src, ln1_g, ln1_b, p_xh);

    // premix u = [A_jj x_j ; sum_k A_jk x_k]
    premix<<<NB, dim3(32, NJ)>>>(p_xh, p_u);

    // fused: out = LN2(x + u @ Wcat + b_gcn) -> fp32
    ln_gemm_t<16, true, false><<<BJ / 64, 512, LNG_SMEM>>>(p_u, p_Wcat, bgcn, p_xh, ln2_g, ln2_b, out);
}

// round 12
// speedup vs baseline: 1.0663x; 1.0230x over previous
#include <cuda_runtime.h>
#include <cuda_fp16.h>
#include <cstdint>
#include <cstddef>

// Problem constants
#define BJ   69632           // 4096*17 rows
#define NB   4096
#define NJ   17
#define ND   512
#define NH   8
#define NDK  64
#define HALF_ROWS (BJ / 2)   // 34816
#define HALF_B    (NB / 2)   // 2048

// ---------------- device scratch ------------------------------------------------
__device__ __half g_src_h[(size_t)BJ * 512];
__device__ __half g_qkv  [(size_t)BJ * 1536];
__device__ __half g_o    [(size_t)BJ * 512];
__device__ __half g_x_h  [(size_t)BJ * 512];
__device__ __half g_u    [(size_t)BJ * 1024];
__device__ __half g_Wqkv[1536 * 512];
__device__ float  g_bqkv[1536];
__device__ __half g_Wo_t[512 * 512];
__device__ __half g_Wcat[512 * 1024];
__device__ float  g_A[NJ * NJ];

// ---------------- helpers -------------------------------------------------------
__device__ __forceinline__ uint32_t smem_u32(const void* p) {
    uint32_t a;
    asm("{ .reg .u64 t; cvta.to.shared.u64 t, %1; cvt.u32.u64 %0, t; }" : "=r"(a) : "l"(p));
    return a;
}
__device__ __forceinline__ void cp16(uint32_t saddr, const void* gptr) {
    asm volatile("cp.async.cg.shared.global [%0], [%1], 16;" :: "r"(saddr), "l"(gptr));
}
__device__ __forceinline__ void cp_commit() { asm volatile("cp.async.commit_group;" ::: "memory"); }
__device__ __forceinline__ void cp_wait1()  { asm volatile("cp.async.wait_group 1;" ::: "memory"); }
__device__ __forceinline__ void cp_wait0()  { asm volatile("cp.async.wait_group 0;" ::: "memory"); }

__device__ __forceinline__ void ldsm4(uint32_t* r, uint32_t addr) {
    asm volatile("ldmatrix.sync.aligned.m8n8.x4.shared.b16 {%0,%1,%2,%3}, [%4];"
        : "=r"(r[0]), "=r"(r[1]), "=r"(r[2]), "=r"(r[3]) : "r"(addr));
}
__device__ __forceinline__ void mma_f16(float* d, const uint32_t* a, const uint32_t* b) {
    asm volatile(
        "mma.sync.aligned.m16n8k16.row.col.f32.f16.f16.f32 "
        "{%0,%1,%2,%3}, {%4,%5,%6,%7}, {%8,%9}, {%0,%1,%2,%3};"
        : "+f"(d[0]), "+f"(d[1]), "+f"(d[2]), "+f"(d[3])
        : "r"(a[0]), "r"(a[1]), "r"(a[2]), "r"(a[3]), "r"(b[0]), "r"(b[1]));
}

// ================= fp16 mma.sync GEMM ===========================================
#define STAGE_BYTES 32768
#define GEMM_SMEM   (3 * STAGE_BYTES)

__global__ __launch_bounds__(256, 2) void tc_gemm(const __half* __restrict__ A,
                                                  const __half* __restrict__ Bt,
                                                  const float* __restrict__ bias,
                                                  __half* __restrict__ C, int N) {
    extern __shared__ char smem[];
    const uint32_t sb = smem_u32(smem);
    const int tid  = threadIdx.x;
    const int lane = tid & 31;
    const int wid  = tid >> 5;
    const int warp_m = (wid & 1) * 64;
    const int warp_n = (wid >> 1) * 32;
    const int l7 = lane & 7;
    const int a_row_base = warp_m + l7 + ((lane & 8) ? 8 : 0);
    const int a_cc_add = (lane & 16) ? 1 : 0;
    const int b_row_base = warp_n + l7 + ((lane & 16) ? 8 : 0);
    const int b_cc_add = (lane & 8) ? 1 : 0;

    const __half* Abase = A  + (size_t)blockIdx.y * 128 * 512;
    const __half* Bbase = Bt + (size_t)blockIdx.x * 128 * 512;

    auto issue = [&](int t) {
        const int buf = t % 3;
        const uint32_t sA = sb + buf * STAGE_BYTES;
        const uint32_t sB = sA + 16384;
        const __half* Ab = Abase + t * 64;
        const __half* Bb = Bbase + t * 64;
        #pragma unroll
        for (int ll = 0; ll < 4; ++ll) {
            int id = tid + ll * 256, row = id >> 3, cc = id & 7;
            cp16(sA + row * 128 + ((cc ^ (row & 7)) << 4), Ab + (size_t)row * 512 + cc * 8);
        }
        #pragma unroll
        for (int ll = 0; ll < 4; ++ll) {
            int id = tid + ll * 256, row = id >> 3, cc = id & 7;
            cp16(sB + row * 128 + ((cc ^ (row & 7)) << 4), Bb + (size_t)row * 512 + cc * 8);
        }
        cp_commit();
    };

    float acc[4][4][4];
    #pragma unroll
    for (int i = 0; i < 4; ++i)
        #pragma unroll
        for (int j = 0; j < 4; ++j)
            #pragma unroll
            for (int q = 0; q < 4; ++q) acc[i][j][q] = 0.f;

    issue(0);
    issue(1);

    #pragma unroll 1
    for (int t = 0; t < 8; ++t) {
        if (t < 7) cp_wait1(); else cp_wait0();
        __syncthreads();
        if (t + 2 < 8) issue(t + 2);

        const int buf = t % 3;
        const uint32_t sA = sb + buf * STAGE_BYTES;
        const uint32_t sB = sA + 16384;

        #pragma unroll
        for (int q = 0; q < 4; ++q) {
            const int kc = 2 * q;
            uint32_t af[4][4], bf[2][4];
            #pragma unroll
            for (int i = 0; i < 4; ++i)
                ldsm4(af[i], sA + (uint32_t)(a_row_base + i * 16) * 128 +
                              (uint32_t)(((kc + a_cc_add) ^ l7) << 4));
            #pragma unroll
            for (int j2 = 0; j2 < 2; ++j2)
                ldsm4(bf[j2], sB + (uint32_t)(b_row_base + j2 * 16) * 128 +
                               (uint32_t)(((kc + b_cc_add) ^ l7) << 4));
            #pragma unroll
            for (int i = 0; i < 4; ++i)
                #pragma unroll
                for (int j = 0; j < 4; ++j)
                    mma_f16(acc[i][j], af[i], &bf[j >> 1][(j & 1) * 2]);
        }
    }

    const size_t rowBase = (size_t)blockIdx.y * 128 + warp_m + (lane >> 2);
    const int colBase = blockIdx.x * 128 + warp_n + (lane & 3) * 2;
    #pragma unroll
    for (int i = 0; i < 4; ++i) {
        #pragma unroll
        for (int j = 0; j < 4; ++j) {
            size_t m0 = rowBase + i * 16;
            int n0 = colBase + j * 8;
            float b0 = bias[n0], b1 = bias[n0 + 1];
            *(__half2*)(C + m0 * (size_t)N + n0) =
                __floats2half2_rn(acc[i][j][0] + b0, acc[i][j][1] + b1);
            *(__half2*)(C + (m0 + 8) * (size_t)N + n0) =
                __floats2half2_rn(acc[i][j][2] + b0, acc[i][j][3] + b1);
        }
    }
}

// ===== fused GEMM + bias + residual + LayerNorm (full 512-wide rows) ============
#define LNG_STAGE (8192 + 65536)
#define LNG_SMEM  (3 * LNG_STAGE)

template<int NCHUNK, bool RES_HALF, bool OUT_HALF>
__global__ __launch_bounds__(512) void ln_gemm_t(const __half* __restrict__ A,
                                                 const __half* __restrict__ Bt,
                                                 const float* __restrict__ bias,
                                                 const void* __restrict__ resid,
                                                 const float* __restrict__ gam,
                                                 const float* __restrict__ bet,
                                                 void* __restrict__ outp) {
    constexpr int K = NCHUNK * 64;
    extern __shared__ char smem[];
    const uint32_t sb = smem_u32(smem);
    const int tid  = threadIdx.x;
    const int lane = tid & 31;
    const int wid  = tid >> 5;
    const int warp_m = (wid & 1) * 32;
    const int wid_n  = wid >> 1;
    const int warp_n = wid_n * 64;
    const int l7 = lane & 7;
    const int a_row_base = warp_m + l7 + ((lane & 8) ? 8 : 0);
    const int a_cc_add = (lane & 16) ? 1 : 0;
    const int b_row_base = warp_n + l7 + ((lane & 16) ? 8 : 0);
    const int b_cc_add = (lane & 8) ? 1 : 0;

    const size_t rowBlk = (size_t)blockIdx.x * 64;
    const __half* Abase = A + rowBlk * K;

    auto issue = [&](int t) {
        const int buf = t % 3;
        const uint32_t sA = sb + buf * LNG_STAGE;
        const uint32_t sB = sA + 8192;
        const __half* Ab = Abase + t * 64;
        const __half* Bb = Bt + t * 64;
        {
            int row = tid >> 3, cc = tid & 7;
            cp16(sA + row * 128 + ((cc ^ (row & 7)) << 4), Ab + (size_t)row * K + cc * 8);
        }
        #pragma unroll
        for (int ll = 0; ll < 8; ++ll) {
            int id = tid + ll * 512, row = id >> 3, cc = id & 7;
            cp16(sB + row * 128 + ((cc ^ (row & 7)) << 4), Bb + (size_t)row * K + cc * 8);
        }
        cp_commit();
    };

    float acc[2][8][4];
    #pragma unroll
    for (int i = 0; i < 2; ++i)
        #pragma unroll
        for (int j = 0; j < 8; ++j)
            #pragma unroll
            for (int q = 0; q < 4; ++q) acc[i][j][q] = 0.f;

    issue(0);
    issue(1);

    #pragma unroll 1
    for (int t = 0; t < NCHUNK; ++t) {
        if (t < NCHUNK - 1) cp_wait1(); else cp_wait0();
        __syncthreads();
        if (t + 2 < NCHUNK) issue(t + 2);

        const int buf = t % 3;
        const uint32_t sA = sb + buf * LNG_STAGE;
        const uint32_t sB = sA + 8192;

        #pragma unroll
        for (int q = 0; q < 4; ++q) {
            const int kc = 2 * q;
            uint32_t af[2][4], bf[4][4];
            #pragma unroll
            for (int i = 0; i < 2; ++i)
                ldsm4(af[i], sA + (uint32_t)(a_row_base + i * 16) * 128 +
                              (uint32_t)(((kc + a_cc_add) ^ l7) << 4));
            #pragma unroll
            for (int j2 = 0; j2 < 4; ++j2)
                ldsm4(bf[j2], sB + (uint32_t)(b_row_base + j2 * 16) * 128 +
                               (uint32_t)(((kc + b_cc_add) ^ l7) << 4));
            #pragma unroll
            for (int i = 0; i < 2; ++i)
                #pragma unroll
                for (int j = 0; j < 8; ++j)
                    mma_f16(acc[i][j], af[i], &bf[j >> 1][(j & 1) * 2]);
        }
    }
    __syncthreads();

    float2* red  = (float2*)smem;
    float2* stat = (float2*)(smem + 4096);
    const int rq = lane >> 2;
    const int cq = (lane & 3) * 2;

    #pragma unroll
    for (int i = 0; i < 2; ++i) {
        #pragma unroll
        for (int h2 = 0; h2 < 2; ++h2) {
            int row_local = warp_m + i * 16 + h2 * 8 + rq;
            size_t grow = (rowBlk + row_local) * 512;
            float s = 0.f, ss = 0.f;
            #pragma unroll
            for (int j = 0; j < 8; ++j) {
                int col = warp_n + cq + j * 8;
                float2 sv;
                if (RES_HALF)
                    sv = __half22float2(*(const __half2*)((const __half*)resid + grow + col));
                else
                    sv = *(const float2*)((const float*)resid + grow + col);
                float v0 = acc[i][j][h2 * 2 + 0] + bias[col]     + sv.x;
                float v1 = acc[i][j][h2 * 2 + 1] + bias[col + 1] + sv.y;
                acc[i][j][h2 * 2 + 0] = v0;
                acc[i][j][h2 * 2 + 1] = v1;
                s += v0 + v1;
                ss = fmaf(v0, v0, ss); ss = fmaf(v1, v1, ss);
            }
            s  += __shfl_xor_sync(0xffffffffu, s, 1);  s  += __shfl_xor_sync(0xffffffffu, s, 2);
            ss += __shfl_xor_sync(0xffffffffu, ss, 1); ss += __shfl_xor_sync(0xffffffffu, ss, 2);
            if ((lane & 3) == 0) red[row_local * 8 + wid_n] = make_float2(s, ss);
        }
    }
    __syncthreads();
    if (tid < 64) {
        float s = 0.f, ss = 0.f;
        #pragma unroll
        for (int w = 0; w < 8; ++w) {
            float2 v = red[tid * 8 + w];
            s += v.x; ss += v.y;
        }
        float mean = s * (1.0f / 512.0f);
        float var  = ss * (1.0f / 512.0f) - mean * mean;
        stat[tid] = make_float2(mean, rsqrtf(var + 1e-5f));
    }
    __syncthreads();
    #pragma unroll
    for (int i = 0; i < 2; ++i) {
        #pragma unroll
        for (int h2 = 0; h2 < 2; ++h2) {
            int row_local = warp_m + i * 16 + h2 * 8 + rq;
            float2 st = stat[row_local];
            size_t grow = (rowBlk + row_local) * 512;
            #pragma unroll
            for (int j = 0; j < 8; ++j) {
                int col = warp_n + cq + j * 8;
                float y0 = (acc[i][j][h2 * 2 + 0] - st.x) * st.y * gam[col]     + bet[col];
                float y1 = (acc[i][j][h2 * 2 + 1] - st.x) * st.y * gam[col + 1] + bet[col + 1];
                if (OUT_HALF)
                    *(__half2*)((__half*)outp + grow + col) = __floats2half2_rn(y0, y1);
                else
                    *(float2*)((float*)outp + grow + col) = make_float2(y0, y1);
            }
        }
    }
}

// ---------------- src -> half (float4 per thread, offset form) ------------------
__global__ void conv_src(const float* __restrict__ src, __half* __restrict__ dst, int n4) {
    int idx = blockIdx.x * blockDim.x + threadIdx.x;
    if (idx >= n4) return;
    float4 v = *(const float4*)(src + (size_t)idx * 4);
    __half2 a = __floats2half2_rn(v.x, v.y);
    __half2 b = __floats2half2_rn(v.z, v.w);
    uint2 w;
    w.x = *(uint32_t*)&a;
    w.y = *(uint32_t*)&b;
    *(uint2*)(dst + (size_t)idx * 4) = w;
}

// ---------------- weight packing ------------------------------------------------
__global__ void pack_qkv_w(const float* __restrict__ Wq, const float* __restrict__ Wk,
                           const float* __restrict__ Wv, const float* __restrict__ bq,
                           const float* __restrict__ bk, const float* __restrict__ bv) {
    int idx = blockIdx.x * blockDim.x + threadIdx.x;
    if (idx >= 512 * 1536) return;
    int d = idx / 1536, cc2 = idx % 1536;
    int sel = cc2 / 512, cc = cc2 % 512;
    int h = cc / 64, e = cc % 64;
    const float* W = (sel == 0) ? Wq : (sel == 1) ? Wk : Wv;
    g_Wqkv[(size_t)cc2 * 512 + d] = __float2half_rn(W[((size_t)h * 512 + d) * 64 + e]);
    if (d == 0) {
        const float* bb = (sel == 0) ? bq : (sel == 1) ? bk : bv;
        g_bqkv[cc2] = bb[cc];
    }
}

__global__ void pack_wo(const float* __restrict__ Wo) {
    int idx = blockIdx.x * blockDim.x + threadIdx.x;
    if (idx >= 512 * 512) return;
    int n = idx / 512, k = idx % 512;
    g_Wo_t[idx] = __float2half_rn(Wo[(size_t)k * 512 + n]);
}

__global__ void pack_wcat(const float* __restrict__ Wgcn) {
    int idx = blockIdx.x * blockDim.x + threadIdx.x;
    if (idx >= 512 * 1024) return;
    int n = idx / 1024, k = idx % 1024;
    float v;
    if (k < 512) v = Wgcn[(size_t)k * 512 + n] - Wgcn[262144 + (size_t)k * 512 + n];
    else         v = Wgcn[262144 + (size_t)(k - 512) * 512 + n];
    g_Wcat[idx] = __float2half_rn(v);
}

// ---------------- adjacency softmax ---------------------------------------------
__global__ void build_A(const int* __restrict__ rows, const int* __restrict__ cols,
                        const float* __restrict__ e, int nnz) {
    __shared__ float lg[NJ][NJ];
    int tid = threadIdx.x;
    if (tid < NJ * NJ) lg[tid / NJ][tid % NJ] = -9e15f;
    __syncthreads();
    if (tid < nnz) lg[rows[tid]][cols[tid]] = e[tid];
    __syncthreads();
    if (tid < NJ) {
        float m = -9e15f;
        #pragma unroll
        for (int k = 0; k < NJ; k++) m = fmaxf(m, lg[tid][k]);
        float ex[NJ]; float s = 0.f;
        #pragma unroll
        for (int k = 0; k < NJ; k++) { ex[k] = __expf(lg[tid][k] - m); s += ex[k]; }
        float inv = 1.0f / s;
        #pragma unroll
        for (int k = 0; k < NJ; k++) g_A[tid * NJ + k] = ex[k] * inv;
    }
}

// ---------------- attention: one block per batch, 9 warps, half2 smem -----------
#define QLD 257
#define KLD 259
#define VLD 257
#define ATTN_SMEM (NJ * (QLD + KLD + VLD) * 4)

__global__ __launch_bounds__(288) void attn_kernel(const __half* __restrict__ qkv,
                                                   __half* __restrict__ o) {
    extern __shared__ uint32_t sm2[];
    uint32_t* qs = sm2;
    uint32_t* ks = qs + NJ * QLD;
    uint32_t* vs = ks + NJ * KLD;

    int b = blockIdx.x;
    int tid = threadIdx.x;
    const uint32_t* base = (const uint32_t*)(qkv + (size_t)b * NJ * 1536);

    for (int i = tid; i < NJ * 768; i += 288) {
        int row = i / 768, c = i % 768;
        uint32_t w = base[row * 768 + c];
        if (c < 256)      qs[row * QLD + c]        = w;
        else if (c < 512) ks[row * KLD + (c - 256)] = w;
        else              vs[row * VLD + (c - 512)] = w;
    }
    __syncthreads();

    int wrp = tid >> 5, lane = tid & 31;
    #pragma unroll 1
    for (int rep = 0; rep < 2; ++rep) {
        int j = wrp + rep * 9;
        if (j >= NJ) break;
        __half* orow = o + ((size_t)(b * NJ + j)) * 512;

        #pragma unroll 1
        for (int h = 0; h < NH; ++h) {
            const int hw = h * 32;
            float s = -1e30f;
            if (lane < NJ) {
                const uint32_t* qp = qs + j * QLD + hw;
                const uint32_t* kp = ks + lane * KLD + hw;
                float acc = 0.f;
                #pragma unroll
                for (int e = 0; e < 32; ++e) {
                    float2 qv = __half22float2(*(const __half2*)&qp[e]);
                    float2 kv = __half22float2(*(const __half2*)&kp[e]);
                    acc = fmaf(qv.x, kv.x, fmaf(qv.y, kv.y, acc));
                }
                s = acc * 0.125f;
            }
            float m = s;
            #pragma unroll
            for (int off = 16; off; off >>= 1) m = fmaxf(m, __shfl_xor_sync(0xffffffffu, m, off));
            float p = (lane < NJ) ? __expf(s - m) : 0.f;
            float sum = p;
            #pragma unroll
            for (int off = 16; off; off >>= 1) sum += __shfl_xor_sync(0xffffffffu, sum, off);
            p *= (1.0f / sum);

            const int wsel = lane & 1;
            const int widx = hw + (lane >> 1);
            float o0 = 0.f, o1 = 0.f;
            #pragma unroll
            for (int k = 0; k < NJ; ++k) {
                float pk = __shfl_sync(0xffffffffu, p, k);
                __half2 w0 = *(__half2*)&vs[k * VLD + widx];
                __half2 w1 = *(__half2*)&vs[k * VLD + widx + 16];
                float v0 = wsel ? __high2float(w0) : __low2float(w0);
                float v1 = wsel ? __high2float(w1) : __low2float(w1);
                o0 = fmaf(pk, v0, o0);
                o1 = fmaf(pk, v1, o1);
            }
            orow[h * 64 + lane]      = __float2half_rn(o0);
            orow[h * 64 + lane + 32] = __float2half_rn(o1);
        }
    }
}

// ---------------- premix: u_j = [A_jj*x_j ; sum_k A_jk*x_k] ---------------------
__global__ __launch_bounds__(544) void premix(const __half* __restrict__ x,
                                              __half* __restrict__ u) {
    int b = blockIdx.x;
    __shared__ float xs[NJ][512];
    __shared__ float Arow[NJ][NJ];
    __shared__ float Ad[NJ];
    int tid = threadIdx.y * 32 + threadIdx.x;
    for (int i = tid; i < NJ * 256; i += 544) {
        int k = i >> 8, e2 = i & 255;
        float2 v = __half22float2(*(const __half2*)(x + ((size_t)(b * NJ + k)) * 512 + e2 * 2));
        xs[k][e2 * 2] = v.x; xs[k][e2 * 2 + 1] = v.y;
    }
    if (tid < NJ * NJ) {
        int j = tid / NJ, k = tid % NJ;
        float a = g_A[tid];
        Arow[j][k] = a;
        if (j == k) Ad[j] = a;
    }
    __syncthreads();

    int j = threadIdx.y, lane = threadIdx.x;
    __half* ur = u + ((size_t)(b * NJ + j)) * 1024;
    float adiag = Ad[j];
    #pragma unroll
    for (int t = 0; t < 16; t++) {
        int d = lane + (t << 5);
        float z = 0.f;
        #pragma unroll
        for (int k = 0; k < NJ; k++) z = fmaf(Arow[j][k], xs[k][d], z);
        ur[d]       = __float2half_rn(adiag * xs[j][d]);
        ur[512 + d] = __float2half_rn(z);
    }
}

// ---------------- host launcher --------------------------------------------------
extern "C" void kernel_launch(void* const* d_in, const int* in_sizes, int n_in,
                              void* d_out, int out_size) {
    const float* src   = (const float*)d_in[0];
    const float* Wq    = (const float*)d_in[1];
    const float* bq    = (const float*)d_in[2];
    const float* Wk    = (const float*)d_in[3];
    const float* bk    = (const float*)d_in[4];
    const float* Wv    = (const float*)d_in[5];
    const float* bv    = (const float*)d_in[6];
    const float* Wo    = (const float*)d_in[7];
    const float* bo    = (const float*)d_in[8];
    const float* ln1_g = (const float*)d_in[9];
    const float* ln1_b = (const float*)d_in[10];
    const float* Wgcn  = (const float*)d_in[11];
    const float* egcn  = (const float*)d_in[12];
    const float* bgcn  = (const float*)d_in[13];
    const float* ln2_g = (const float*)d_in[14];
    const float* ln2_b = (const float*)d_in[15];
    const int*   mrows = (const int*)d_in[16];
    const int*   mcols = (const int*)d_in[17];
    int nnz = in_sizes[16];
    float* out = (float*)d_out;

    __half *p_srch, *p_qkv, *p_o, *p_xh, *p_u, *p_Wqkv, *p_Wot, *p_Wcat;
    float *p_bqkv;
    cudaGetSymbolAddress((void**)&p_srch, g_src_h);
    cudaGetSymbolAddress((void**)&p_qkv,  g_qkv);
    cudaGetSymbolAddress((void**)&p_o,    g_o);
    cudaGetSymbolAddress((void**)&p_xh,   g_x_h);
    cudaGetSymbolAddress((void**)&p_u,    g_u);
    cudaGetSymbolAddress((void**)&p_Wqkv, g_Wqkv);
    cudaGetSymbolAddress((void**)&p_bqkv, g_bqkv);
    cudaGetSymbolAddress((void**)&p_Wot,  g_Wo_t);
    cudaGetSymbolAddress((void**)&p_Wcat, g_Wcat);

    static cudaStream_t s_side = nullptr, s_side2 = nullptr, s_c1 = nullptr;
    static cudaEvent_t e_fork = nullptr, e_join = nullptr, e_join2 = nullptr, e_c1 = nullptr;
    if (!s_side) {
        cudaStreamCreateWithFlags(&s_side, cudaStreamNonBlocking);
        cudaStreamCreateWithFlags(&s_side2, cudaStreamNonBlocking);
        cudaStreamCreateWithFlags(&s_c1, cudaStreamNonBlocking);
        cudaEventCreateWithFlags(&e_fork, cudaEventDisableTiming);
        cudaEventCreateWithFlags(&e_join, cudaEventDisableTiming);
        cudaEventCreateWithFlags(&e_join2, cudaEventDisableTiming);
        cudaEventCreateWithFlags(&e_c1, cudaEventDisableTiming);
        cudaFuncSetAttribute(tc_gemm, cudaFuncAttributeMaxDynamicSharedMemorySize, GEMM_SMEM);
        cudaFuncSetAttribute(ln_gemm_t<8,  false, true >, cudaFuncAttributeMaxDynamicSharedMemorySize, LNG_SMEM);
        cudaFuncSetAttribute(ln_gemm_t<16, true,  false>, cudaFuncAttributeMaxDynamicSharedMemorySize, LNG_SMEM);
        cudaFuncSetAttribute(attn_kernel, cudaFuncAttributeMaxDynamicSharedMemorySize, ATTN_SMEM);
    }

    // ---- fork: side branches for weight packing
    cudaEventRecord(e_fork, 0);
    cudaStreamWaitEvent(s_side, e_fork, 0);
    cudaStreamWaitEvent(s_side2, e_fork, 0);
    cudaStreamWaitEvent(s_c1, e_fork, 0);
    pack_wo<<<(512 * 512 + 255) / 256, 256, 0, s_side>>>(Wo);
    pack_wcat<<<(512 * 1024 + 255) / 256, 256, 0, s_side>>>(Wgcn);
    build_A<<<1, 512, 0, s_side>>>(mrows, mcols, egcn, nnz);
    cudaEventRecord(e_join, s_side);

    pack_qkv_w<<<(512 * 1536 + 255) / 256, 256, 0, s_side2>>>(Wq, Wk, Wv, bq, bk, bv);
    cudaEventRecord(e_join2, s_side2);

    // ---- two independent half-chains: chain0 on stream 0, chain1 on s_c1
    for (int half = 0; half < 2; ++half) {
        cudaStream_t st = half ? s_c1 : (cudaStream_t)0;
        const size_t r0 = (size_t)half * HALF_ROWS;            // row offset
        const float*  srcH  = src    + r0 * 512;
        __half*       srchH = p_srch + r0 * 512;
        __half*       qkvH  = p_qkv  + r0 * 1536;
        __half*       oH    = p_o    + r0 * 512;
        __half*       xhH   = p_xh   + r0 * 512;
        __half*       uH    = p_u    + r0 * 1024;
        float*        outH  = out    + r0 * 512;

        conv_src<<<(HALF_ROWS * 128 + 255) / 256, 256, 0, st>>>(srcH, srchH, HALF_ROWS * 128);
        cudaStreamWaitEvent(st, e_join2, 0);
        tc_gemm<<<dim3(1536 / 128, HALF_ROWS / 128), 256, GEMM_SMEM, st>>>(srchH, p_Wqkv, p_bqkv, qkvH, 1536);
        attn_kernel<<<HALF_B, 288, ATTN_SMEM, st>>>(qkvH, oH);
        cudaStreamWaitEvent(st, e_join, 0);
        ln_gemm_t<8, false, true><<<HALF_ROWS / 64, 512, LNG_SMEM, st>>>(oH, p_Wot, bo, srcH, ln1_g, ln1_b, xhH);
        premix<<<HALF_B, dim3(32, NJ), 0, st>>>(xhH, uH);
        ln_gemm_t<16, true, false><<<HALF_ROWS / 64, 512, LNG_SMEM, st>>>(uH, p_Wcat, bgcn, xhH, ln2_g, ln2_b, outH);
    }

    // ---- join chain1 back into the default stream
    cudaEventRecord(e_c1, s_c1);
    cudaStreamWaitEvent(0, e_c1, 0);
}